// round 17
// baseline (speedup 1.0000x reference)
#include <cuda_runtime.h>
#include <math.h>

#define N_NODES 50000
#define N_EDGES 800000
#define H 64
#define S 16
#define EF 16
#define ATT_W 144
#define UPD_W 128
#define CSR_BLOCKS 148
#define CSR_CH 338          // ceil(50000/148)

typedef unsigned long long ULL;

// ---------------- scratch (static device allocations) ----------------
// +32 pad: allows unpredicated tail loads (statics zero-initialized; pad
// never written; tail contributions multiplied by zero weights).
__device__ float g_Psrc[N_NODES * ATT_W + 32];
__device__ float g_Pdst[N_NODES * ATT_W + 32];   // includes att_b1 folded in
__device__ float g_raw[N_EDGES];            // CSR-ordered raw scores
__device__ float g_agg[N_NODES * H];
__device__ int   g_deg[N_NODES];
__device__ int   g_rowptr[N_NODES + 1];
__device__ int   g_cursor[N_NODES];
__device__ int   g_es[N_EDGES];             // CSR-ordered original edge id
__device__ int   g_ss[N_EDGES];             // CSR-ordered src
__device__ int   g_ds[N_EDGES];             // CSR-ordered dst
__device__ int   g_bsum[CSR_BLOCKS];
__device__ unsigned int g_count;

// ---------------- f32x2 packed helpers ----------------
__device__ __forceinline__ ULL pk2(float lo, float hi) {
    ULL r;
    asm("mov.b64 %0, {%1, %2};" : "=l"(r) : "f"(lo), "f"(hi));
    return r;
}
__device__ __forceinline__ void upk2(ULL v, float& lo, float& hi) {
    asm("mov.b64 {%0, %1}, %2;" : "=f"(lo), "=f"(hi) : "l"(v));
}
__device__ __forceinline__ ULL ffma2(ULL a, ULL b, ULL c) {
    ULL d;
    asm("fma.rn.f32x2 %0, %1, %2, %3;" : "=l"(d) : "l"(a), "l"(b), "l"(c));
    return d;
}
__device__ __forceinline__ float red2(ULL v) {
    float lo, hi; upk2(v, lo, hi); return lo + hi;
}

// ---------------- CSR: reset then fused build ----------------
__global__ void csr_reset_kernel() {
    int i = blockIdx.x * blockDim.x + threadIdx.x;
    if (i < N_NODES) { g_deg[i] = 0; g_cursor[i] = 0; }
    if (i == 0) g_count = 0u;
}

__device__ __forceinline__ void gbar(int phase) {
    __syncthreads();
    if (threadIdx.x == 0) {
        __threadfence();
        atomicAdd(&g_count, 1u);
        while (*((volatile unsigned int*)&g_count) < (unsigned)(phase * CSR_BLOCKS)) { }
        __threadfence();
    }
    __syncthreads();
}

__global__ void __launch_bounds__(512) csr_build_kernel(const int* __restrict__ ei) {
    __shared__ int ssum[512];
    __shared__ int boff[CSR_BLOCKS];
    int t = threadIdx.x;
    int gid = blockIdx.x * 512 + t;

    // phase 1: degree histogram
    for (int e = gid; e < N_EDGES; e += CSR_BLOCKS * 512)
        atomicAdd(&g_deg[ei[N_EDGES + e]], 1);
    gbar(1);

    // phase 2: per-block inclusive scan of this block's node chunk
    int nbase = blockIdx.x * CSR_CH;
    int node = nbase + t;
    int dv = 0;
    if (t < CSR_CH && node < N_NODES) dv = g_deg[node];
    ssum[t] = dv;
    __syncthreads();
    for (int off = 1; off < 512; off <<= 1) {
        int v = (t >= off) ? ssum[t - off] : 0;
        __syncthreads();
        ssum[t] += v;
        __syncthreads();
    }
    int incl = ssum[t];
    if (t == 511) g_bsum[blockIdx.x] = ssum[511];
    gbar(2);

    // phase 3: exclusive scan of block sums, write rowptr
    if (t < CSR_BLOCKS) boff[t] = g_bsum[t];
    __syncthreads();
    if (t == 0) {
        int run = 0;
        for (int b = 0; b < CSR_BLOCKS; b++) { int tmp = boff[b]; boff[b] = run; run += tmp; }
    }
    __syncthreads();
    int myoff = boff[blockIdx.x];
    if (t < CSR_CH && node < N_NODES) g_rowptr[node] = myoff + incl - dv;
    if (blockIdx.x == 0 && t == 0) g_rowptr[N_NODES] = N_EDGES;
    gbar(3);

    // phase 4: fill (CSR-ordered edge id + src + dst)
    for (int e = gid; e < N_EDGES; e += CSR_BLOCKS * 512) {
        int s = ei[e];
        int d = ei[N_EDGES + e];
        int pos = g_rowptr[d] + atomicAdd(&g_cursor[d], 1);
        g_es[pos] = e;
        g_ss[pos] = s;
        g_ds[pos] = d;
    }
}

// ---------------- node projections (FFMA2 register-tiled GEMM) ----------------
// Weights pre-packed over f pairs: Wp[fp][j] = (w[j][2fp], w[j][2fp+1]).
// Activations read as direct ULL loads (stride 82 floats = 328B, 8B-aligned;
// only 8B accesses touch Xs). b1 folded into Pdst.
__global__ void __launch_bounds__(288, 2) proj_kernel(
        const float* __restrict__ x, const float* __restrict__ xs,
        const float* __restrict__ w1, const float* __restrict__ b1) {
    extern __shared__ ULL smu[];
    ULL* Wp = smu;                      // [fp][j]: 40 x 288 ULL
    float* Xs = (float*)(Wp + 40 * 288);// [n][f]: 16 x 82 (even stride, 8B ok)
    __shared__ float b1s[144];
    int tid = threadIdx.x;

    for (int idx = tid; idx < 40 * 288; idx += blockDim.x) {
        int j = idx % 288, fp = idx / 288;
        int jr = (j < 144) ? j : j - 144;
        int f0 = 2 * fp, f1 = 2 * fp + 1;
        int c0, c1;
        if (j < 144) { c0 = (f0 < 64) ? f0 : 64 + f0; c1 = (f1 < 64) ? f1 : 64 + f1; }
        else         { c0 = (f0 < 64) ? 64 + f0 : 80 + f0; c1 = (f1 < 64) ? 64 + f1 : 80 + f1; }
        Wp[fp * 288 + j] = pk2(w1[jr * 176 + c0], w1[jr * 176 + c1]);
    }
    if (tid < 144) b1s[tid] = b1[tid];
    __syncthreads();

    int tj = tid >> 3;      // 0..35
    int tn = tid & 7;       // 0..7
    const int NCH = N_NODES / 16;   // 3125 exact

    for (int c = blockIdx.x; c < NCH; c += gridDim.x) {
        int n0 = c * 16;
        for (int idx = tid; idx < 16 * 80; idx += blockDim.x) {
            int n = idx / 80, f = idx % 80;
            int nd = n0 + n;
            Xs[n * 82 + f] = (f < 64) ? x[nd * 64 + f] : xs[nd * 16 + (f - 64)];
        }
        __syncthreads();

        ULL acc[8][2];
#pragma unroll
        for (int jj = 0; jj < 8; jj++) { acc[jj][0] = 0ull; acc[jj][1] = 0ull; }

        for (int fp = 0; fp < 40; fp++) {
            const ULL* wrow = &Wp[fp * 288 + tj * 8];
            ULL x0 = *(const ULL*)&Xs[(tn * 2 + 0) * 82 + 2 * fp];
            ULL x1 = *(const ULL*)&Xs[(tn * 2 + 1) * 82 + 2 * fp];
#pragma unroll
            for (int jj = 0; jj < 8; jj++) {
                ULL w = wrow[jj];
                acc[jj][0] = ffma2(w, x0, acc[jj][0]);
                acc[jj][1] = ffma2(w, x1, acc[jj][1]);
            }
        }

#pragma unroll
        for (int u = 0; u < 2; u++) {
            int nd = n0 + tn * 2 + u;
            int j = tj * 8;
            if (j < 144) {
                float4 o0 = {red2(acc[0][u]), red2(acc[1][u]), red2(acc[2][u]), red2(acc[3][u])};
                float4 o1 = {red2(acc[4][u]), red2(acc[5][u]), red2(acc[6][u]), red2(acc[7][u])};
                *(float4*)&g_Psrc[nd * 144 + j] = o0;
                *(float4*)&g_Psrc[nd * 144 + j + 4] = o1;
            } else {
                int jb = j - 144;
                float4 o0 = {red2(acc[0][u]) + b1s[jb + 0], red2(acc[1][u]) + b1s[jb + 1],
                             red2(acc[2][u]) + b1s[jb + 2], red2(acc[3][u]) + b1s[jb + 3]};
                float4 o1 = {red2(acc[4][u]) + b1s[jb + 4], red2(acc[5][u]) + b1s[jb + 5],
                             red2(acc[6][u]) + b1s[jb + 6], red2(acc[7][u]) + b1s[jb + 7]};
                *(float4*)&g_Pdst[nd * 144 + jb] = o0;
                *(float4*)&g_Pdst[nd * 144 + jb + 4] = o1;
            }
        }
        __syncthreads();
    }
}

// ---------------- edge score kernel: smem ef staging + ps/pd prefetch ---------
__global__ void __launch_bounds__(128, 4) score_kernel(
        const float* __restrict__ ef,
        const float* __restrict__ w1,
        const float* __restrict__ w2, const float* __restrict__ b2) {
    __shared__ float part[4][32 * 33];
    __shared__ __align__(16) float efs[4][32][20];
    int tid = threadIdx.x;
    int lane = tid & 31;
    int wip = tid >> 5;
    float* myPart = part[wip];
    float (*myEfs)[20] = efs[wip];

    ULL wP[8][4];
    ULL wT[8];
    float w2r[4], w2t;
#pragma unroll
    for (int jj = 0; jj < 4; jj++) {
        int j = 4 * lane + jj;
        w2r[jj] = w2[j];
#pragma unroll
        for (int fp = 0; fp < 8; fp++)
            wP[fp][jj] = pk2(w1[j * 176 + 160 + 2 * fp], w1[j * 176 + 160 + 2 * fp + 1]);
    }
    {
        int j = 128 + lane;
        bool v = (lane < 16);
        w2t = v ? w2[j] : 0.f;
#pragma unroll
        for (int fp = 0; fp < 8; fp++) {
            float wlo = v ? w1[j * 176 + 160 + 2 * fp] : 0.f;
            float whi = v ? w1[j * 176 + 160 + 2 * fp + 1] : 0.f;
            wT[fp] = pk2(wlo, whi);
        }
    }
    float b2v = b2[0];

    int gw = (blockIdx.x * blockDim.x + tid) >> 5;
    int nw = (gridDim.x * blockDim.x) >> 5;
    int chunk = (N_EDGES + nw - 1) / nw;
    int p0 = gw * chunk;
    int p1 = min(p0 + chunk, N_EDGES);

    for (int cb = p0; cb < p1; cb += 32) {
        int cd = min(32, p1 - cb);

        {
            int eL = g_es[cb + ((lane < cd) ? lane : 0)];
            const float4* src = (const float4*)(ef + (size_t)eL * 16);
            float4 v0 = src[0], v1 = src[1], v2 = src[2], v3 = src[3];
            *(float4*)&myEfs[lane][0]  = v0;
            *(float4*)&myEfs[lane][4]  = v1;
            *(float4*)&myEfs[lane][8]  = v2;
            *(float4*)&myEfs[lane][12] = v3;
        }
        __syncwarp();

        float4 ps4, pd4; float pst, pdt;
        {
            int s = g_ss[cb], d = g_ds[cb];
            const float* psrow = &g_Psrc[(size_t)s * 144];
            const float* pdrow = &g_Pdst[(size_t)d * 144];
            ps4 = *(const float4*)&psrow[4 * lane];
            pd4 = *(const float4*)&pdrow[4 * lane];
            pst = psrow[128 + lane];
            pdt = pdrow[128 + lane];
        }

        for (int t = 0; t < cd; t++) {
            float4 cps = ps4, cpd = pd4;
            float cpst = pst, cpdt = pdt;

            if (t + 1 < cd) {
                int s = g_ss[cb + t + 1], d = g_ds[cb + t + 1];
                const float* psrow = &g_Psrc[(size_t)s * 144];
                const float* pdrow = &g_Pdst[(size_t)d * 144];
                ps4 = *(const float4*)&psrow[4 * lane];
                pd4 = *(const float4*)&pdrow[4 * lane];
                pst = psrow[128 + lane];
                pdt = pdrow[128 + lane];
            }

            const float4* er = (const float4*)&myEfs[t][0];
            float4 e0 = er[0], e1 = er[1], e2 = er[2], e3 = er[3];
            ULL efp[8];
            efp[0] = pk2(e0.x, e0.y); efp[1] = pk2(e0.z, e0.w);
            efp[2] = pk2(e1.x, e1.y); efp[3] = pk2(e1.z, e1.w);
            efp[4] = pk2(e2.x, e2.y); efp[5] = pk2(e2.z, e2.w);
            efp[6] = pk2(e3.x, e3.y); efp[7] = pk2(e3.z, e3.w);

            ULL a0 = pk2(cps.x, cpd.x);
            ULL a1 = pk2(cps.y, cpd.y);
            ULL a2 = pk2(cps.z, cpd.z);
            ULL a3 = pk2(cps.w, cpd.w);
            ULL aT = pk2(cpst, cpdt);
#pragma unroll
            for (int fp = 0; fp < 8; fp++) {
                ULL v = efp[fp];
                a0 = ffma2(v, wP[fp][0], a0);
                a1 = ffma2(v, wP[fp][1], a1);
                a2 = ffma2(v, wP[fp][2], a2);
                a3 = ffma2(v, wP[fp][3], a3);
                aT = ffma2(v, wT[fp], aT);
            }
            float pr;
            pr = fmaxf(red2(a0), 0.f) * w2r[0];
            pr = fmaf(fmaxf(red2(a1), 0.f), w2r[1], pr);
            pr = fmaf(fmaxf(red2(a2), 0.f), w2r[2], pr);
            pr = fmaf(fmaxf(red2(a3), 0.f), w2r[3], pr);
            pr = fmaf(fmaxf(red2(aT), 0.f), w2t,   pr);

            myPart[t * 33 + lane] = pr;
        }
        __syncwarp();

        if (lane < cd) {
            const float* row = &myPart[lane * 33];
            float s0 = 0.f, s1 = 0.f, s2 = 0.f, s3 = 0.f;
#pragma unroll
            for (int i = 0; i < 32; i += 4) {
                s0 += row[i + 0];
                s1 += row[i + 1];
                s2 += row[i + 2];
                s3 += row[i + 3];
            }
            float r = (s0 + s1) + (s2 + s3) + b2v;
            r = (r > 0.f) ? r : 0.01f * r;
            g_raw[cb + lane] = r;
        }
        __syncwarp();
    }
}

// ---------------- segment softmax + weighted aggregation ----------------
__global__ void softagg_kernel(const float* __restrict__ x) {
    int warp = (blockIdx.x * blockDim.x + threadIdx.x) >> 5;
    int lane = threadIdx.x & 31;
    if (warp >= N_NODES) return;
    int start = g_rowptr[warp];
    int deg = g_rowptr[warp + 1] - start;

    float m = -1e30f;
    for (int i = lane; i < deg; i += 32) m = fmaxf(m, g_raw[start + i]);
#pragma unroll
    for (int o = 16; o; o >>= 1) m = fmaxf(m, __shfl_xor_sync(0xffffffffu, m, o));

    float acc0 = 0.f, acc1 = 0.f, ws = 0.f;
    for (int base = 0; base < deg; base += 32) {
        int i = base + lane;
        float w = (i < deg) ? __expf(g_raw[start + i] - m) : 0.f;
        int sv = (i < deg) ? g_ss[start + i] : 0;
        ws += w;
        int cnt = min(32, deg - base);
        for (int t = 0; t < cnt; t++) {
            float wt = __shfl_sync(0xffffffffu, w, t);
            int st = __shfl_sync(0xffffffffu, sv, t);
            acc0 = fmaf(wt, x[(size_t)st * 64 + lane], acc0);
            acc1 = fmaf(wt, x[(size_t)st * 64 + 32 + lane], acc1);
        }
    }
#pragma unroll
    for (int o = 16; o; o >>= 1) ws += __shfl_xor_sync(0xffffffffu, ws, o);
    float scale = 1.f / (ws + 1e-9f);
    g_agg[warp * 64 + lane] = acc0 * scale;
    g_agg[warp * 64 + 32 + lane] = acc1 * scale;
}

// ---------------- fused 2-layer update MLP (FFMA2 register-tiled) ----------------
// W1p packed over f pairs, W2p packed over j pairs; Hs stored [n][j] so stage2
// reads j-pairs as direct ULL loads. Row stride 132 floats = 528 bytes:
// divisible by 16 -> float4 stores aligned for every row (130 was the R14 trap).
__global__ void __launch_bounds__(256, 1) update_kernel(
        const float* __restrict__ x,
        const float* __restrict__ w1, const float* __restrict__ b1,
        const float* __restrict__ w2, const float* __restrict__ b2,
        float* __restrict__ out) {
    extern __shared__ ULL smu[];
    ULL* W1p = smu;                         // [fp][j]: 64 x 128 ULL
    ULL* W2p = W1p + 64 * 128;              // [jp][o]: 64 x 64 ULL
    float* Xs = (float*)(W2p + 64 * 64);    // [n][f]: 64 x 132
    float* Hs = Xs + 64 * 132;              // [n][j]: 64 x 132
    float* b1s = Hs + 64 * 132;             // 128
    float* b2s = b1s + 128;                 // 64
    int tid = threadIdx.x;

    for (int idx = tid; idx < 64 * 128; idx += 256) {
        int fp = idx >> 7, j = idx & 127;
        W1p[fp * 128 + j] = pk2(w1[j * 128 + 2 * fp], w1[j * 128 + 2 * fp + 1]);
    }
    for (int idx = tid; idx < 64 * 64; idx += 256) {
        int jp = idx >> 6, o = idx & 63;
        W2p[jp * 64 + o] = pk2(w2[o * 128 + 2 * jp], w2[o * 128 + 2 * jp + 1]);
    }
    if (tid < 128) b1s[tid] = b1[tid];
    if (tid < 64) b2s[tid] = b2[tid];
    __syncthreads();

    int tn = tid & 15;
    int tj = tid >> 4;
    const int NCH = (N_NODES + 63) / 64;

    for (int c = blockIdx.x; c < NCH; c += gridDim.x) {
        int n0 = c * 64;
        for (int idx = tid; idx < 64 * 128; idx += 256) {
            int n = idx >> 7, f = idx & 127;
            int nd = n0 + n;
            float v = 0.f;
            if (nd < N_NODES)
                v = (f < 64) ? x[nd * 64 + f] : g_agg[nd * 64 + (f - 64)];
            Xs[n * 132 + f] = v;
        }
        __syncthreads();

        {   // stage 1: H[n][j] = relu(W1 @ X + b1); thread: 8 j x 4 n
            ULL acc[8][4];
#pragma unroll
            for (int jj = 0; jj < 8; jj++)
#pragma unroll
                for (int nn = 0; nn < 4; nn++) acc[jj][nn] = 0ull;

            for (int fp = 0; fp < 64; fp++) {
                const ULL* wrow = &W1p[fp * 128 + tj * 8];
                ULL xv[4];
#pragma unroll
                for (int nn = 0; nn < 4; nn++)
                    xv[nn] = *(const ULL*)&Xs[(tn * 4 + nn) * 132 + 2 * fp];
#pragma unroll
                for (int jj = 0; jj < 8; jj++) {
                    ULL w = wrow[jj];
#pragma unroll
                    for (int nn = 0; nn < 4; nn++)
                        acc[jj][nn] = ffma2(w, xv[nn], acc[jj][nn]);
                }
            }
#pragma unroll
            for (int nn = 0; nn < 4; nn++) {
                int n = tn * 4 + nn;
                float4 h0 = {fmaxf(red2(acc[0][nn]) + b1s[tj * 8 + 0], 0.f),
                             fmaxf(red2(acc[1][nn]) + b1s[tj * 8 + 1], 0.f),
                             fmaxf(red2(acc[2][nn]) + b1s[tj * 8 + 2], 0.f),
                             fmaxf(red2(acc[3][nn]) + b1s[tj * 8 + 3], 0.f)};
                float4 h1 = {fmaxf(red2(acc[4][nn]) + b1s[tj * 8 + 4], 0.f),
                             fmaxf(red2(acc[5][nn]) + b1s[tj * 8 + 5], 0.f),
                             fmaxf(red2(acc[6][nn]) + b1s[tj * 8 + 6], 0.f),
                             fmaxf(red2(acc[7][nn]) + b1s[tj * 8 + 7], 0.f)};
                *(float4*)&Hs[n * 132 + tj * 8] = h0;
                *(float4*)&Hs[n * 132 + tj * 8 + 4] = h1;
            }
        }
        __syncthreads();

        {   // stage 2: out[n][o] = relu(W2 @ H + b2); thread: 4 o x 4 n
            int to = tid & 15;
            int tn2 = tid >> 4;
            ULL acc2[4][4];     // [nn][oo]
#pragma unroll
            for (int nn = 0; nn < 4; nn++)
#pragma unroll
                for (int oo = 0; oo < 4; oo++) acc2[nn][oo] = 0ull;

            for (int jp = 0; jp < 64; jp++) {
                const ULL* wrow = &W2p[jp * 64 + to * 4];
                ULL hv[4];
#pragma unroll
                for (int nn = 0; nn < 4; nn++)
                    hv[nn] = *(const ULL*)&Hs[(tn2 * 4 + nn) * 132 + 2 * jp];
#pragma unroll
                for (int oo = 0; oo < 4; oo++) {
                    ULL w = wrow[oo];
#pragma unroll
                    for (int nn = 0; nn < 4; nn++)
                        acc2[nn][oo] = ffma2(w, hv[nn], acc2[nn][oo]);
                }
            }
#pragma unroll
            for (int nn = 0; nn < 4; nn++) {
                int nd = n0 + tn2 * 4 + nn;
                if (nd < N_NODES) {
                    float4 ov = {fmaxf(red2(acc2[nn][0]) + b2s[to * 4 + 0], 0.f),
                                 fmaxf(red2(acc2[nn][1]) + b2s[to * 4 + 1], 0.f),
                                 fmaxf(red2(acc2[nn][2]) + b2s[to * 4 + 2], 0.f),
                                 fmaxf(red2(acc2[nn][3]) + b2s[to * 4 + 3], 0.f)};
                    *(float4*)&out[nd * 64 + to * 4] = ov;
                }
            }
        }
        __syncthreads();
    }
}

// ---------------- launch ----------------
extern "C" void kernel_launch(void* const* d_in, const int* in_sizes, int n_in,
                              void* d_out, int out_size) {
    const float* x      = (const float*)d_in[0];
    const float* x_s    = (const float*)d_in[1];
    const int*   eidx   = (const int*)d_in[2];
    const float* efeat  = (const float*)d_in[3];
    const float* att_w1 = (const float*)d_in[4];
    const float* att_b1 = (const float*)d_in[5];
    const float* att_w2 = (const float*)d_in[6];
    const float* att_b2 = (const float*)d_in[7];
    const float* upd_w1 = (const float*)d_in[8];
    const float* upd_b1 = (const float*)d_in[9];
    const float* upd_w2 = (const float*)d_in[10];
    const float* upd_b2 = (const float*)d_in[11];
    float* out = (float*)d_out;

    const int PROJ_SMEM = 40 * 288 * 8 + 16 * 82 * 4;                       // ~97.4 KB
    const int UPD_SMEM  = 64 * 128 * 8 + 64 * 64 * 8 + 64 * 132 * 4 * 2 + (128 + 64) * 4; // ~167 KB
    cudaFuncSetAttribute(proj_kernel, cudaFuncAttributeMaxDynamicSharedMemorySize, PROJ_SMEM);
    cudaFuncSetAttribute(update_kernel, cudaFuncAttributeMaxDynamicSharedMemorySize, UPD_SMEM);

    // CSR build
    csr_reset_kernel<<<(N_NODES + 1023) / 1024, 1024>>>();
    csr_build_kernel<<<CSR_BLOCKS, 512>>>(eidx);

    // node projections (FFMA2-packed, b1 folded into Pdst)
    proj_kernel<<<296, 288, PROJ_SMEM>>>(x, x_s, att_w1, att_b1);

    // edge attention scores (smem ef staging + ps/pd prefetch, single wave)
    score_kernel<<<592, 128>>>(efeat, att_w1, att_w2, att_b2);

    // segment softmax + aggregation
    softagg_kernel<<<(N_NODES * 32 + 255) / 256, 256>>>(x);

    // update MLP (FFMA2-packed, aligned strides)
    update_kernel<<<148, 256, UPD_SMEM>>>(x, upd_w1, upd_b1, upd_w2, upd_b2, out);
}